// round 8
// baseline (speedup 1.0000x reference)
#include <cuda_runtime.h>
#include <math.h>

#define NB    64
#define CCH   256
#define HW    2816     // 64*44 per channel
#define WW    44
#define PPX   176
#define TOPKK 22
#define TEMP_INV 8.0f
#define GATE_THR 0.05f
#define THREADS 512
#define NUNITS 108     // 22 smap + 64 token + 22 pmap

#define TOK_ELEMS   (NB*CCH*64)
#define PRES_ELEMS  (NB*64)
#define MAP_ELEMS   (NB*64*44*64)

typedef unsigned long long u64;

__device__ int g_cnt[NB];   // zero-init; self-resetting each launch

struct __align__(16) SM {
    float lbn8[CCH*8];      // normalized basis, k-duplicated pairs {x,x,y,y,z,z,w,w}
    float pdP[4*PPX*4];     // dotp partials per channel-subset [cs][p][k]
    float feP[4*PPX];
    float nrmP[4*PPX];
    float sup[PPX*4];
    float pw[PPX*4];
    float pwT[4*PPX];       // transposed pool weights [k][p]
    float red[32];
    float scal[16];
    int   ctr;
    int   flag;
};

__device__ __forceinline__ float wsum(float v) {
#pragma unroll
    for (int o = 16; o; o >>= 1) v += __shfl_xor_sync(0xffffffffu, v, o);
    return v;
}
__device__ __forceinline__ float wmaxr(float v) {
#pragma unroll
    for (int o = 16; o; o >>= 1) v = fmaxf(v, __shfl_xor_sync(0xffffffffu, v, o));
    return v;
}
__device__ __forceinline__ u64 pk2(float lo, float hi) {
    u64 r; asm("mov.b64 %0,{%1,%2};" : "=l"(r) : "f"(lo), "f"(hi)); return r;
}
__device__ __forceinline__ void up2(u64 v, float& a, float& b) {
    asm("mov.b64 {%0,%1},%2;" : "=f"(a), "=f"(b) : "l"(v));
}
__device__ __forceinline__ u64 ffma2(u64 a, u64 b, u64 c) {
    u64 d; asm("fma.rn.f32x2 %0,%1,%2,%3;" : "=l"(d) : "l"(a), "l"(b), "l"(c)); return d;
}
__device__ __forceinline__ u64 fadd2(u64 a, u64 b) {
    u64 d; asm("add.rn.f32x2 %0,%1,%2;" : "=l"(d) : "l"(a), "l"(b)); return d;
}

__global__ void __launch_bounds__(THREADS, 3)
fused_stripe_kernel(const float* __restrict__ x, const float* __restrict__ lb,
                    float* __restrict__ out_tok, float* __restrict__ out_pres,
                    float* __restrict__ out_smap, float* __restrict__ out_pmap)
{
    __shared__ SM s;
    const unsigned FULL = 0xffffffffu;
    const int tid = threadIdx.x, lane = tid & 31, wid = tid >> 5;
    const int blk = blockIdx.x;
    const int n = blk >> 4, g = blk & 15;
    const float* xb = x + (size_t)n * (CCH * HW) + (size_t)g * PPX;

    // ---------- Phase 1: load + L2-normalize latent basis (k-duplicated layout) ----------
    {
        if (tid == 0) { s.ctr = 0; s.flag = 0; }
        if (tid < 256) {
            const float* lbg = lb + (size_t)g * (4 * CCH);
            float v0 = lbg[tid], v1 = lbg[CCH + tid], v2 = lbg[2 * CCH + tid], v3 = lbg[3 * CCH + tid];
            float s0 = wsum(v0 * v0), s1 = wsum(v1 * v1), s2 = wsum(v2 * v2), s3 = wsum(v3 * v3);
            if (lane == 0) { s.red[wid] = s0; s.red[8 + wid] = s1; s.red[16 + wid] = s2; s.red[24 + wid] = s3; }
            __syncthreads();
            if (tid < 4) {
                float ss = 0.f;
#pragma unroll
                for (int j = 0; j < 8; ++j) ss += s.red[tid * 8 + j];
                s.scal[tid] = 1.0f / fmaxf(sqrtf(ss), 1e-12f);
            }
            __syncthreads();
            float ox = v0 * s.scal[0], oy = v1 * s.scal[1], oz = v2 * s.scal[2], ow = v3 * s.scal[3];
            *reinterpret_cast<float4*>(&s.lbn8[tid * 8 + 0]) = make_float4(ox, ox, oy, oy);
            *reinterpret_cast<float4*>(&s.lbn8[tid * 8 + 4]) = make_float4(oz, oz, ow, ow);
        } else {
            __syncthreads();
            __syncthreads();
        }
        __syncthreads();
    }

    // ---------- Phase 2: float2-lane stencil pass from GMEM (16 warps) ----------
    // warp: r = row (0..3), cs = channel subset (0..3, 64 contiguous channels each)
    // lanes 0..21 active: lane j covers pixels (r*44 + 2j, +1)
    {
        const int r = wid & 3, cs = wid >> 2;
        const bool act2 = (lane < 22);
        const int po = r * WW + (act2 ? lane * 2 : 0);
        const bool ha = act2 && (r > 0), hc = act2 && (r < 3);
        const float fq0 = (lane > 0) ? 1.f : 0.f, fq21 = (lane < 21) ? 1.f : 0.f;

        u64 pd0 = 0, pd1 = 0, pd2 = 0, pd3 = 0, fe = 0, nr = 0;
        const float* pc = xb + po + (size_t)(cs * 64) * HW;

        // prologue loads
        u64 xm0 = act2 ? *reinterpret_cast<const u64*>(pc) : 0ull;
        u64 xu0 = ha ? *reinterpret_cast<const u64*>(pc - WW) : 0ull;
        u64 xd0 = hc ? *reinterpret_cast<const u64*>(pc + WW) : 0ull;

        const int cbase = cs * 64;
#pragma unroll 1
        for (int i = 0; i < 64; ++i) {
            u64 xm = xm0, xu = xu0, xd = xd0;
            pc += HW;
            const bool more = (i < 63);
            xm0 = (act2 && more) ? *reinterpret_cast<const u64*>(pc) : 0ull;
            xu0 = (ha && more)   ? *reinterpret_cast<const u64*>(pc - WW) : 0ull;
            xd0 = (hc && more)   ? *reinterpret_cast<const u64*>(pc + WW) : 0ull;

            u64 vs2 = fadd2(fadd2(xu, xm), xd);
            float v0, v1;
            up2(vs2, v0, v1);
            float lw = __shfl_up_sync(FULL, v1, 1) * fq0;
            float rw = __shfl_down_sync(FULL, v0, 1) * fq21;
            float t = v0 + v1;
            u64 pl = pk2(lw + t, t + rw);

            const ulonglong2* lb8 = reinterpret_cast<const ulonglong2*>(&s.lbn8[(cbase + i) * 8]);
            ulonglong2 lxy = lb8[0], lzw = lb8[1];
            pd0 = ffma2(pl, lxy.x, pd0);
            pd1 = ffma2(pl, lxy.y, pd1);
            pd2 = ffma2(pl, lzw.x, pd2);
            pd3 = ffma2(pl, lzw.y, pd3);
            fe  = ffma2(xm, xm, fe);
            nr  = ffma2(pl, pl, nr);
        }
        if (act2) {
            float p00, p01, p10, p11, p20, p21, p30, p31, f0, f1, n0, n1;
            up2(pd0, p00, p01); up2(pd1, p10, p11);
            up2(pd2, p20, p21); up2(pd3, p30, p31);
            up2(fe, f0, f1);    up2(nr, n0, n1);
            float* pb = &s.pdP[(cs * PPX + po) * 4];
            *reinterpret_cast<float4*>(pb + 0) = make_float4(p00, p10, p20, p30);
            *reinterpret_cast<float4*>(pb + 4) = make_float4(p01, p11, p21, p31);
            *reinterpret_cast<float2*>(&s.feP[cs * PPX + po])  = make_float2(f0, f1);
            *reinterpret_cast<float2*>(&s.nrmP[cs * PPX + po]) = make_float2(n0, n1);
        }
    }
    __syncthreads();

    // ---------- Phase 2b: combine partials + fused fe-max ----------
    float dotv0 = 0, dotv1 = 0, dotv2 = 0, dotv3 = 0, fev = 0, nmv = 0;
    if (tid < PPX) {
#pragma unroll
        for (int cs = 0; cs < 4; ++cs) {
            float4 v = *reinterpret_cast<float4*>(&s.pdP[(cs * PPX + tid) * 4]);
            dotv0 += v.x; dotv1 += v.y; dotv2 += v.z; dotv3 += v.w;
            fev += s.feP[cs * PPX + tid];
            nmv += s.nrmP[cs * PPX + tid];
        }
        fev *= (1.0f / CCH);
        nmv *= (1.0f / 81.0f);
    }
    {
        float m = wmaxr((tid < PPX) ? fev : 0.f);
        if (lane == 0) s.red[wid] = m;
    }
    __syncthreads();
    float invmax;
    {
        float mm = s.red[0];
#pragma unroll
        for (int j = 1; j < 16; ++j) mm = fmaxf(mm, s.red[j]);
        invmax = 1.0f / fmaxf(mm, 1e-6f);
    }
    int pred = (tid < PPX) && (fev * invmax > GATE_THR);
    int cnt = __syncthreads_count(pred);

    // ---------- Phase 4: softmax routing -> support ----------
    if (tid < PPX) {
        float rn = 1.0f / fmaxf(sqrtf(nmv), 1e-12f);
        float sc = rn * TEMP_INV * (1.f / 9.f);
        float l0 = dotv0 * sc, l1 = dotv1 * sc, l2 = dotv2 * sc, l3 = dotv3 * sc;
        float m = fmaxf(fmaxf(l0, l1), fmaxf(l2, l3));
        float e0 = __expf(l0 - m), e1 = __expf(l1 - m), e2 = __expf(l2 - m), e3 = __expf(l3 - m);
        float inv = 1.0f / (e0 + e1 + e2 + e3);
        float fes = fev * invmax;
        float act = (cnt > 0) ? (fes > GATE_THR ? 1.f : 0.f) : (fes > 0.f ? 1.f : 0.f);
        float w_ = inv * act;
        *reinterpret_cast<float4*>(&s.sup[tid * 4]) = make_float4(e0 * w_, e1 * w_, e2 * w_, e3 * w_);
    }
    __syncthreads();

    // ---------- Phase 5: overlapped tail ----------
    float* smb = out_smap + (size_t)n * (HW * 64) + (size_t)g * (PPX * 64);
    float* pmb = out_pmap + (size_t)n * (HW * 64) + (size_t)g * (PPX * 64);

    if (wid == 0) {
        float s0 = 0, s1 = 0, s2 = 0, s3 = 0;
        for (int pp = lane; pp < PPX; pp += 32) {
            float4 v = *reinterpret_cast<float4*>(&s.sup[pp * 4]);
            s0 += v.x; s1 += v.y; s2 += v.z; s3 += v.w;
        }
        s0 = wsum(s0); s1 = wsum(s1); s2 = wsum(s2); s3 = wsum(s3);
        float i0 = 1.0f / fmaxf(s0, 1e-6f), i1 = 1.0f / fmaxf(s1, 1e-6f);
        float i2 = 1.0f / fmaxf(s2, 1e-6f), i3 = 1.0f / fmaxf(s3, 1e-6f);
        for (int pp = lane; pp < PPX; pp += 32) {
            float4 v = *reinterpret_cast<float4*>(&s.sup[pp * 4]);
            float4 w = make_float4(v.x * i0, v.y * i1, v.z * i2, v.w * i3);
            *reinterpret_cast<float4*>(&s.pw[pp * 4]) = w;
            s.pwT[0 * PPX + pp] = w.x;
            s.pwT[1 * PPX + pp] = w.y;
            s.pwT[2 * PPX + pp] = w.z;
            s.pwT[3 * PPX + pp] = w.w;
        }
        __threadfence_block();
        if (lane == 0) s.flag = 1;
    } else if (wid >= 4 && wid < 8) {
        const int k = wid - 4;
        float v[6];
#pragma unroll
        for (int j = 0; j < 6; ++j) {
            int pp = lane + 32 * j;
            v[j] = (pp < PPX) ? s.sup[pp * 4 + k] : -1.0f;
        }
        float sum = 0.f;
        for (int it = 0; it < TOPKK; ++it) {
            float lm = v[0]; int li = 0;
#pragma unroll
            for (int j = 1; j < 6; ++j) { if (v[j] > lm) { lm = v[j]; li = j; } }
            float wm = wmaxr(lm);
            unsigned msk = __ballot_sync(FULL, lm == wm);
            int src = __ffs(msk) - 1;
            if (lane == src) v[li] = -1.0f;
            sum += wm;
        }
        if (lane == 0) {
            out_pres[n * 64 + g * 4 + k] = sum * (1.0f / TOPKK);
            __threadfence();
        }
    }

    // work queue: units [0,22)=smap, [22,86)=tokens, [86,108)=pmap
    {
        const float4 z4 = make_float4(0.f, 0.f, 0.f, 0.f);
        bool pwReady = false;
        for (;;) {
            int u;
            if (lane == 0) u = atomicAdd(&s.ctr, 1);
            u = __shfl_sync(FULL, u, 0);
            if (u >= NUNITS) break;
            if (u >= 22 && !pwReady) {
                while (*((volatile int*)&s.flag) == 0) {}
                __threadfence_block();
                pwReady = true;
            }
            if (u < 22) {
                int base = u * 128;
#pragma unroll
                for (int j = 0; j < 4; ++j) {
                    int idx = base + j * 32 + lane;
                    int pp = idx >> 4, qd = idx & 15;
                    float4 sv = (qd == g) ? *reinterpret_cast<float4*>(&s.sup[pp * 4]) : z4;
                    *reinterpret_cast<float4*>(smb + (size_t)idx * 4) = sv;
                }
            } else if (u < 86) {
                const int grp = lane >> 3, gl = lane & 7;
                const int c = (u - 22) * 4 + grp;
                const float* xc = xb + (size_t)c * HW;
                u64 a0 = 0, a1 = 0, a2 = 0, a3 = 0;
#pragma unroll
                for (int it = 0; it < 6; ++it) {
                    int p0 = it * 32 + gl * 4;
                    if (p0 < PPX) {
                        ulonglong2 xv = *reinterpret_cast<const ulonglong2*>(xc + p0);
                        ulonglong2 w0 = *reinterpret_cast<const ulonglong2*>(&s.pwT[0 * PPX + p0]);
                        ulonglong2 w1 = *reinterpret_cast<const ulonglong2*>(&s.pwT[1 * PPX + p0]);
                        ulonglong2 w2 = *reinterpret_cast<const ulonglong2*>(&s.pwT[2 * PPX + p0]);
                        ulonglong2 w3 = *reinterpret_cast<const ulonglong2*>(&s.pwT[3 * PPX + p0]);
                        a0 = ffma2(xv.y, w0.y, ffma2(xv.x, w0.x, a0));
                        a1 = ffma2(xv.y, w1.y, ffma2(xv.x, w1.x, a1));
                        a2 = ffma2(xv.y, w2.y, ffma2(xv.x, w2.x, a2));
                        a3 = ffma2(xv.y, w3.y, ffma2(xv.x, w3.x, a3));
                    }
                }
                float x0, y0, x1, y1, x2, y2, x3, y3;
                up2(a0, x0, y0); up2(a1, x1, y1); up2(a2, x2, y2); up2(a3, x3, y3);
                float f0 = x0 + y0, f1 = x1 + y1, f2 = x2 + y2, f3 = x3 + y3;
#pragma unroll
                for (int m = 1; m <= 4; m <<= 1) {
                    f0 += __shfl_xor_sync(FULL, f0, m);
                    f1 += __shfl_xor_sync(FULL, f1, m);
                    f2 += __shfl_xor_sync(FULL, f2, m);
                    f3 += __shfl_xor_sync(FULL, f3, m);
                }
                if (gl == 0)
                    *reinterpret_cast<float4*>(out_tok + ((size_t)(n * CCH + c) * 64 + g * 4)) =
                        make_float4(f0, f1, f2, f3);
            } else {
                int base = (u - 86) * 128;
#pragma unroll
                for (int j = 0; j < 4; ++j) {
                    int idx = base + j * 32 + lane;
                    int pp = idx >> 4, qd = idx & 15;
                    float4 pv = (qd == g) ? *reinterpret_cast<float4*>(&s.pw[pp * 4]) : z4;
                    *reinterpret_cast<float4*>(pmb + (size_t)idx * 4) = pv;
                }
            }
        }
    }

    // ---------- Phase 9: last CTA of batch n normalizes presence ----------
    __syncthreads();
    if (tid == 0) {
        __threadfence();
        int old = atomicAdd(&g_cnt[n], 1);
        s.red[0] = (old == 15) ? 1.f : 0.f;
    }
    __syncthreads();
    if (s.red[0] != 0.f && wid == 0) {
        __threadfence();
        float a = out_pres[n * 64 + lane];
        float b = out_pres[n * 64 + 32 + lane];
        float t = wsum(a + b);
        float inv = 1.0f / fmaxf(t, 1e-6f);
        out_pres[n * 64 + lane] = a * inv;
        out_pres[n * 64 + 32 + lane] = b * inv;
        if (lane == 0) g_cnt[n] = 0;
    }
}

extern "C" void kernel_launch(void* const* d_in, const int* in_sizes, int n_in,
                              void* d_out, int out_size)
{
    const float* x  = (const float*)d_in[0];
    const float* lb = (const float*)d_in[1];
    float* out = (float*)d_out;

    float* tok  = out;
    float* pres = out + TOK_ELEMS;
    float* smap = out + TOK_ELEMS + PRES_ELEMS;
    float* pmap = out + TOK_ELEMS + PRES_ELEMS + MAP_ELEMS;

    fused_stripe_kernel<<<NB * 16, THREADS>>>(x, lb, tok, pres, smap, pmap);
}

// round 9
// speedup vs baseline: 1.1829x; 1.1829x over previous
#include <cuda_runtime.h>
#include <math.h>

#define NB    64
#define CCH   256
#define HW    2816     // 64*44 per channel
#define WW    44
#define PPX   176
#define TOPKK 22
#define TEMP_INV 8.0f
#define GATE_THR 0.05f
#define THREADS 256
#define NUNITS 108     // 22 smap + 64 token + 22 pmap

#define TOK_ELEMS   (NB*CCH*64)
#define PRES_ELEMS  (NB*64)
#define MAP_ELEMS   (NB*64*44*64)

typedef unsigned long long u64;

__device__ int g_cnt[NB];   // zero-init; self-resetting each launch

struct __align__(16) SM {
    float lbn8[CCH*8];      // normalized basis, k-duplicated pairs {x,x,y,y,z,z,w,w}
    float pdP[4*PPX*4];     // dotp partials per channel-subset [cs][p][k]
    float feP[4*PPX];
    float nrmP[4*PPX];
    float sup[PPX*4];
    float pw[PPX*4];
    float pwT[4*PPX];       // transposed pool weights [k][p]
    float red[32];
    float scal[16];
    int   ctr;
    int   flag;
};

__device__ __forceinline__ float wsum(float v) {
#pragma unroll
    for (int o = 16; o; o >>= 1) v += __shfl_xor_sync(0xffffffffu, v, o);
    return v;
}
__device__ __forceinline__ float wmaxr(float v) {
#pragma unroll
    for (int o = 16; o; o >>= 1) v = fmaxf(v, __shfl_xor_sync(0xffffffffu, v, o));
    return v;
}
__device__ __forceinline__ u64 pk2(float lo, float hi) {
    u64 r; asm("mov.b64 %0,{%1,%2};" : "=l"(r) : "f"(lo), "f"(hi)); return r;
}
__device__ __forceinline__ void up2(u64 v, float& a, float& b) {
    asm("mov.b64 {%0,%1},%2;" : "=f"(a), "=f"(b) : "l"(v));
}
__device__ __forceinline__ u64 ffma2(u64 a, u64 b, u64 c) {
    u64 d; asm("fma.rn.f32x2 %0,%1,%2,%3;" : "=l"(d) : "l"(a), "l"(b), "l"(c)); return d;
}
__device__ __forceinline__ u64 fadd2(u64 a, u64 b) {
    u64 d; asm("add.rn.f32x2 %0,%1,%2;" : "=l"(d) : "l"(a), "l"(b)); return d;
}

__global__ void __launch_bounds__(THREADS, 5)
fused_stripe_kernel(const float* __restrict__ x, const float* __restrict__ lb,
                    float* __restrict__ out_tok, float* __restrict__ out_pres,
                    float* __restrict__ out_smap, float* __restrict__ out_pmap)
{
    __shared__ SM s;
    const unsigned FULL = 0xffffffffu;
    const int tid = threadIdx.x, lane = tid & 31, wid = tid >> 5;
    const int blk = blockIdx.x;
    const int n = blk >> 4, g = blk & 15;
    const float* xb = x + (size_t)n * (CCH * HW) + (size_t)g * PPX;

    // ---------- Phase 1: load + L2-normalize latent basis (k-duplicated layout) ----------
    {
        if (tid == 0) { s.ctr = 0; s.flag = 0; }
        const float* lbg = lb + (size_t)g * (4 * CCH);
        float v0 = lbg[tid], v1 = lbg[CCH + tid], v2 = lbg[2 * CCH + tid], v3 = lbg[3 * CCH + tid];
        float s0 = wsum(v0 * v0), s1 = wsum(v1 * v1), s2 = wsum(v2 * v2), s3 = wsum(v3 * v3);
        if (lane == 0) { s.red[wid] = s0; s.red[8 + wid] = s1; s.red[16 + wid] = s2; s.red[24 + wid] = s3; }
        __syncthreads();
        if (tid < 4) {
            float ss = 0.f;
#pragma unroll
            for (int j = 0; j < 8; ++j) ss += s.red[tid * 8 + j];
            s.scal[tid] = 1.0f / fmaxf(sqrtf(ss), 1e-12f);
        }
        __syncthreads();
        float ox = v0 * s.scal[0], oy = v1 * s.scal[1], oz = v2 * s.scal[2], ow = v3 * s.scal[3];
        *reinterpret_cast<float4*>(&s.lbn8[tid * 8 + 0]) = make_float4(ox, ox, oy, oy);
        *reinterpret_cast<float4*>(&s.lbn8[tid * 8 + 4]) = make_float4(oz, oz, ow, ow);
        __syncthreads();
    }

    // ---------- Phase 2: f32x2 stencil pass from GMEM (xm prefetched) ----------
    {
        const int rp = wid >> 2, cs = wid & 3;
        const bool act2 = (lane < 22);
        const int lr = (lane < 22) ? (lane / 11) : 0;
        const int q  = (lane < 22) ? (lane - 11 * lr) : 0;
        const int r  = rp * 2 + lr;
        const int po = act2 ? (r * WW + q * 4) : 0;
        const bool ha = act2 && (r > 0), hc = act2 && (r < 3);
        const float fq0 = (q > 0) ? 1.f : 0.f, fq10 = (q < 10) ? 1.f : 0.f;
        const ulonglong2 zu2 = make_ulonglong2(0ull, 0ull);

        u64 pd0a = 0, pd0b = 0, pd1a = 0, pd1b = 0, pd2a = 0, pd2b = 0, pd3a = 0, pd3b = 0;
        u64 fea = 0, feb = 0, nra = 0, nrb = 0;
        const float* pc = xb + po + (size_t)cs * HW;

        // prefetch only the xm stream (keeps regs <= ~48 for 5 CTAs/SM)
        ulonglong2 xm0 = act2 ? *reinterpret_cast<const ulonglong2*>(pc) : zu2;

#pragma unroll 1
        for (int c = cs; c < CCH; c += 4) {
            ulonglong2 xm = xm0;
            ulonglong2 xu = ha ? *reinterpret_cast<const ulonglong2*>(pc - WW) : zu2;
            ulonglong2 xd = hc ? *reinterpret_cast<const ulonglong2*>(pc + WW) : zu2;
            pc += 4 * HW;
            const bool more = (c + 4 < CCH);
            xm0 = (act2 && more) ? *reinterpret_cast<const ulonglong2*>(pc) : zu2;

            u64 vs01 = fadd2(fadd2(xu.x, xm.x), xd.x);
            u64 vs23 = fadd2(fadd2(xu.y, xm.y), xd.y);
            float v0, v1, v2, v3;
            up2(vs01, v0, v1); up2(vs23, v2, v3);
            float lw = __shfl_up_sync(FULL, v3, 1) * fq0;
            float rw = __shfl_down_sync(FULL, v0, 1) * fq10;
            float p0f = lw + v0 + v1, p1f = v0 + v1 + v2;
            float p2f = v1 + v2 + v3, p3f = v2 + v3 + rw;
            u64 pl01 = pk2(p0f, p1f), pl23 = pk2(p2f, p3f);

            const ulonglong2* lb8 = reinterpret_cast<const ulonglong2*>(&s.lbn8[c * 8]);
            ulonglong2 lxy = lb8[0], lzw = lb8[1];
            pd0a = ffma2(pl01, lxy.x, pd0a); pd0b = ffma2(pl23, lxy.x, pd0b);
            pd1a = ffma2(pl01, lxy.y, pd1a); pd1b = ffma2(pl23, lxy.y, pd1b);
            pd2a = ffma2(pl01, lzw.x, pd2a); pd2b = ffma2(pl23, lzw.x, pd2b);
            pd3a = ffma2(pl01, lzw.y, pd3a); pd3b = ffma2(pl23, lzw.y, pd3b);
            fea = ffma2(xm.x, xm.x, fea);    feb = ffma2(xm.y, xm.y, feb);
            nra = ffma2(pl01, pl01, nra);    nrb = ffma2(pl23, pl23, nrb);
        }
        if (act2) {
            float p0x, p0y, p0z, p0w, p1x, p1y, p1z, p1w;
            float p2x, p2y, p2z, p2w, p3x, p3y, p3z, p3w;
            up2(pd0a, p0x, p0y); up2(pd0b, p0z, p0w);
            up2(pd1a, p1x, p1y); up2(pd1b, p1z, p1w);
            up2(pd2a, p2x, p2y); up2(pd2b, p2z, p2w);
            up2(pd3a, p3x, p3y); up2(pd3b, p3z, p3w);
            float fx, fy, fz, fw, nx, ny, nz, nw;
            up2(fea, fx, fy); up2(feb, fz, fw);
            up2(nra, nx, ny); up2(nrb, nz, nw);
            float* pb = &s.pdP[(cs * PPX + po) * 4];
            *reinterpret_cast<float4*>(pb + 0)  = make_float4(p0x, p1x, p2x, p3x);
            *reinterpret_cast<float4*>(pb + 4)  = make_float4(p0y, p1y, p2y, p3y);
            *reinterpret_cast<float4*>(pb + 8)  = make_float4(p0z, p1z, p2z, p3z);
            *reinterpret_cast<float4*>(pb + 12) = make_float4(p0w, p1w, p2w, p3w);
            *reinterpret_cast<float4*>(&s.feP[cs * PPX + po])  = make_float4(fx, fy, fz, fw);
            *reinterpret_cast<float4*>(&s.nrmP[cs * PPX + po]) = make_float4(nx, ny, nz, nw);
        }
    }
    __syncthreads();

    // ---------- Phase 2b: combine partials + fused fe-max ----------
    float dotv0 = 0, dotv1 = 0, dotv2 = 0, dotv3 = 0, fev = 0, nmv = 0;
    if (tid < PPX) {
#pragma unroll
        for (int cs = 0; cs < 4; ++cs) {
            float4 v = *reinterpret_cast<float4*>(&s.pdP[(cs * PPX + tid) * 4]);
            dotv0 += v.x; dotv1 += v.y; dotv2 += v.z; dotv3 += v.w;
            fev += s.feP[cs * PPX + tid];
            nmv += s.nrmP[cs * PPX + tid];
        }
        fev *= (1.0f / CCH);
        nmv *= (1.0f / 81.0f);
    }
    {
        float m = wmaxr((tid < PPX) ? fev : 0.f);
        if (lane == 0) s.red[wid] = m;
    }
    __syncthreads();
    float invmax;
    {
        float mm = s.red[0];
#pragma unroll
        for (int j = 1; j < 8; ++j) mm = fmaxf(mm, s.red[j]);
        invmax = 1.0f / fmaxf(mm, 1e-6f);
    }
    int pred = (tid < PPX) && (fev * invmax > GATE_THR);
    int cnt = __syncthreads_count(pred);

    // ---------- Phase 4: softmax routing -> support ----------
    if (tid < PPX) {
        float rn = 1.0f / fmaxf(sqrtf(nmv), 1e-12f);
        float sc = rn * TEMP_INV * (1.f / 9.f);
        float l0 = dotv0 * sc, l1 = dotv1 * sc, l2 = dotv2 * sc, l3 = dotv3 * sc;
        float m = fmaxf(fmaxf(l0, l1), fmaxf(l2, l3));
        float e0 = __expf(l0 - m), e1 = __expf(l1 - m), e2 = __expf(l2 - m), e3 = __expf(l3 - m);
        float inv = 1.0f / (e0 + e1 + e2 + e3);
        float fes = fev * invmax;
        float act = (cnt > 0) ? (fes > GATE_THR ? 1.f : 0.f) : (fes > 0.f ? 1.f : 0.f);
        float w_ = inv * act;
        *reinterpret_cast<float4*>(&s.sup[tid * 4]) = make_float4(e0 * w_, e1 * w_, e2 * w_, e3 * w_);
    }
    __syncthreads();

    // ---------- Phase 5: overlapped tail ----------
    float* smb = out_smap + (size_t)n * (HW * 64) + (size_t)g * (PPX * 64);
    float* pmb = out_pmap + (size_t)n * (HW * 64) + (size_t)g * (PPX * 64);

    if (wid == 0) {
        float s0 = 0, s1 = 0, s2 = 0, s3 = 0;
        for (int pp = lane; pp < PPX; pp += 32) {
            float4 v = *reinterpret_cast<float4*>(&s.sup[pp * 4]);
            s0 += v.x; s1 += v.y; s2 += v.z; s3 += v.w;
        }
        s0 = wsum(s0); s1 = wsum(s1); s2 = wsum(s2); s3 = wsum(s3);
        float i0 = 1.0f / fmaxf(s0, 1e-6f), i1 = 1.0f / fmaxf(s1, 1e-6f);
        float i2 = 1.0f / fmaxf(s2, 1e-6f), i3 = 1.0f / fmaxf(s3, 1e-6f);
        for (int pp = lane; pp < PPX; pp += 32) {
            float4 v = *reinterpret_cast<float4*>(&s.sup[pp * 4]);
            float4 w = make_float4(v.x * i0, v.y * i1, v.z * i2, v.w * i3);
            *reinterpret_cast<float4*>(&s.pw[pp * 4]) = w;
            s.pwT[0 * PPX + pp] = w.x;
            s.pwT[1 * PPX + pp] = w.y;
            s.pwT[2 * PPX + pp] = w.z;
            s.pwT[3 * PPX + pp] = w.w;
        }
        __threadfence_block();
        if (lane == 0) s.flag = 1;
    } else if (wid >= 4) {
        const int k = wid - 4;
        float v[6];
#pragma unroll
        for (int j = 0; j < 6; ++j) {
            int pp = lane + 32 * j;
            v[j] = (pp < PPX) ? s.sup[pp * 4 + k] : -1.0f;
        }
        float sum = 0.f;
        for (int it = 0; it < TOPKK; ++it) {
            float lm = v[0]; int li = 0;
#pragma unroll
            for (int j = 1; j < 6; ++j) { if (v[j] > lm) { lm = v[j]; li = j; } }
            float wm = wmaxr(lm);
            unsigned msk = __ballot_sync(FULL, lm == wm);
            int src = __ffs(msk) - 1;
            if (lane == src) v[li] = -1.0f;
            sum += wm;
        }
        if (lane == 0) {
            out_pres[n * 64 + g * 4 + k] = sum * (1.0f / TOPKK);
            __threadfence();
        }
    }

    // work queue: units [0,22)=smap, [22,86)=tokens, [86,108)=pmap
    {
        const float4 z4 = make_float4(0.f, 0.f, 0.f, 0.f);
        bool pwReady = false;
        for (;;) {
            int u;
            if (lane == 0) u = atomicAdd(&s.ctr, 1);
            u = __shfl_sync(FULL, u, 0);
            if (u >= NUNITS) break;
            if (u >= 22 && !pwReady) {
                while (*((volatile int*)&s.flag) == 0) {}
                __threadfence_block();
                pwReady = true;
            }
            if (u < 22) {
                int base = u * 128;
#pragma unroll
                for (int j = 0; j < 4; ++j) {
                    int idx = base + j * 32 + lane;
                    int pp = idx >> 4, qd = idx & 15;
                    float4 sv = (qd == g) ? *reinterpret_cast<float4*>(&s.sup[pp * 4]) : z4;
                    *reinterpret_cast<float4*>(smb + (size_t)idx * 4) = sv;
                }
            } else if (u < 86) {
                const int grp = lane >> 3, gl = lane & 7;
                const int c = (u - 22) * 4 + grp;
                const float* xc = xb + (size_t)c * HW;
                u64 a0 = 0, a1 = 0, a2 = 0, a3 = 0;
#pragma unroll
                for (int it = 0; it < 6; ++it) {
                    int p0 = it * 32 + gl * 4;
                    if (p0 < PPX) {
                        ulonglong2 xv = *reinterpret_cast<const ulonglong2*>(xc + p0);
                        ulonglong2 w0 = *reinterpret_cast<const ulonglong2*>(&s.pwT[0 * PPX + p0]);
                        ulonglong2 w1 = *reinterpret_cast<const ulonglong2*>(&s.pwT[1 * PPX + p0]);
                        ulonglong2 w2 = *reinterpret_cast<const ulonglong2*>(&s.pwT[2 * PPX + p0]);
                        ulonglong2 w3 = *reinterpret_cast<const ulonglong2*>(&s.pwT[3 * PPX + p0]);
                        a0 = ffma2(xv.y, w0.y, ffma2(xv.x, w0.x, a0));
                        a1 = ffma2(xv.y, w1.y, ffma2(xv.x, w1.x, a1));
                        a2 = ffma2(xv.y, w2.y, ffma2(xv.x, w2.x, a2));
                        a3 = ffma2(xv.y, w3.y, ffma2(xv.x, w3.x, a3));
                    }
                }
                float x0, y0, x1, y1, x2, y2, x3, y3;
                up2(a0, x0, y0); up2(a1, x1, y1); up2(a2, x2, y2); up2(a3, x3, y3);
                float f0 = x0 + y0, f1 = x1 + y1, f2 = x2 + y2, f3 = x3 + y3;
#pragma unroll
                for (int m = 1; m <= 4; m <<= 1) {
                    f0 += __shfl_xor_sync(FULL, f0, m);
                    f1 += __shfl_xor_sync(FULL, f1, m);
                    f2 += __shfl_xor_sync(FULL, f2, m);
                    f3 += __shfl_xor_sync(FULL, f3, m);
                }
                if (gl == 0)
                    *reinterpret_cast<float4*>(out_tok + ((size_t)(n * CCH + c) * 64 + g * 4)) =
                        make_float4(f0, f1, f2, f3);
            } else {
                int base = (u - 86) * 128;
#pragma unroll
                for (int j = 0; j < 4; ++j) {
                    int idx = base + j * 32 + lane;
                    int pp = idx >> 4, qd = idx & 15;
                    float4 pv = (qd == g) ? *reinterpret_cast<float4*>(&s.pw[pp * 4]) : z4;
                    *reinterpret_cast<float4*>(pmb + (size_t)idx * 4) = pv;
                }
            }
        }
    }

    // ---------- Phase 9: last CTA of batch n normalizes presence ----------
    __syncthreads();
    if (tid == 0) {
        __threadfence();
        int old = atomicAdd(&g_cnt[n], 1);
        s.red[0] = (old == 15) ? 1.f : 0.f;
    }
    __syncthreads();
    if (s.red[0] != 0.f && wid == 0) {
        __threadfence();
        float a = out_pres[n * 64 + lane];
        float b = out_pres[n * 64 + 32 + lane];
        float t = wsum(a + b);
        float inv = 1.0f / fmaxf(t, 1e-6f);
        out_pres[n * 64 + lane] = a * inv;
        out_pres[n * 64 + 32 + lane] = b * inv;
        if (lane == 0) g_cnt[n] = 0;
    }
}

extern "C" void kernel_launch(void* const* d_in, const int* in_sizes, int n_in,
                              void* d_out, int out_size)
{
    const float* x  = (const float*)d_in[0];
    const float* lb = (const float*)d_in[1];
    float* out = (float*)d_out;

    float* tok  = out;
    float* pres = out + TOK_ELEMS;
    float* smap = out + TOK_ELEMS + PRES_ELEMS;
    float* pmap = out + TOK_ELEMS + PRES_ELEMS + MAP_ELEMS;

    fused_stripe_kernel<<<NB * 16, THREADS>>>(x, lb, tok, pres, smap, pmap);
}

// round 10
// speedup vs baseline: 1.3888x; 1.1740x over previous
#include <cuda_runtime.h>
#include <math.h>

#define NB    64
#define CCH   256
#define HW    2816     // 64*44 per channel
#define WW    44
#define PPX   176
#define TOPKK 22
#define TEMP_INV 8.0f
#define GATE_THR 0.05f
#define THREADS 256
#define NUNITS 108     // 22 smap + 64 token + 22 pmap
#define NSTAGE 4
#define STCH   4       // channels per stage
#define SLOTF  (STCH*PPX)   // floats per ring slot

#define TOK_ELEMS   (NB*CCH*64)
#define PRES_ELEMS  (NB*64)
#define MAP_ELEMS   (NB*64*44*64)

typedef unsigned long long u64;

__device__ int g_cnt[NB];   // zero-init; self-resetting each launch

struct __align__(16) SM {
    float lbn8[CCH*8];      // normalized basis, k-duplicated pairs {x,x,y,y,z,z,w,w}
    float pdP[4*PPX*4];     // dotp partials per channel-subset [cs][p][k]
    float feP[4*PPX];
    float nrmP[4*PPX];
    float sup[PPX*4];
    float pw[PPX*4];
    float pwT[4*PPX];       // transposed pool weights [k][p]
    float red[32];
    float scal[16];
    int   ctr;
    int   flag;
};

#define SMEM_TOTAL ((int)(sizeof(SM) + NSTAGE*SLOTF*sizeof(float)))

__device__ __forceinline__ float wsum(float v) {
#pragma unroll
    for (int o = 16; o; o >>= 1) v += __shfl_xor_sync(0xffffffffu, v, o);
    return v;
}
__device__ __forceinline__ float wmaxr(float v) {
#pragma unroll
    for (int o = 16; o; o >>= 1) v = fmaxf(v, __shfl_xor_sync(0xffffffffu, v, o));
    return v;
}
__device__ __forceinline__ u64 pk2(float lo, float hi) {
    u64 r; asm("mov.b64 %0,{%1,%2};" : "=l"(r) : "f"(lo), "f"(hi)); return r;
}
__device__ __forceinline__ void up2(u64 v, float& a, float& b) {
    asm("mov.b64 {%0,%1},%2;" : "=f"(a), "=f"(b) : "l"(v));
}
__device__ __forceinline__ u64 ffma2(u64 a, u64 b, u64 c) {
    u64 d; asm("fma.rn.f32x2 %0,%1,%2,%3;" : "=l"(d) : "l"(a), "l"(b), "l"(c)); return d;
}
__device__ __forceinline__ u64 fadd2(u64 a, u64 b) {
    u64 d; asm("add.rn.f32x2 %0,%1,%2;" : "=l"(d) : "l"(a), "l"(b)); return d;
}
__device__ __forceinline__ void fill_stage(float* slot, const float* xb, int c0, int tid) {
    if (tid < STCH * 44) {
        int ch = tid / 44, q = tid - 44 * ch;
        const float* src = xb + (size_t)(c0 + ch) * HW + q * 4;
        unsigned daddr = (unsigned)__cvta_generic_to_shared(slot + ch * PPX + q * 4);
        asm volatile("cp.async.cg.shared.global [%0],[%1],16;" :: "r"(daddr), "l"(src));
    }
}

__global__ void __launch_bounds__(THREADS, 4)
fused_stripe_kernel(const float* __restrict__ x, const float* __restrict__ lb,
                    float* __restrict__ out_tok, float* __restrict__ out_pres,
                    float* __restrict__ out_smap, float* __restrict__ out_pmap)
{
    extern __shared__ char smraw[];
    SM& s = *reinterpret_cast<SM*>(smraw);
    float* ring = reinterpret_cast<float*>(smraw + sizeof(SM));
    const unsigned FULL = 0xffffffffu;
    const int tid = threadIdx.x, lane = tid & 31, wid = tid >> 5;
    const int blk = blockIdx.x;
    const int n = blk >> 4, g = blk & 15;
    const float* xb = x + (size_t)n * (CCH * HW) + (size_t)g * PPX;

    // ---------- Prologue: kick off first 3 stage fills (overlaps phase 1) ----------
#pragma unroll
    for (int ss = 0; ss < 3; ++ss) {
        fill_stage(ring + ss * SLOTF, xb, ss * STCH, tid);
        asm volatile("cp.async.commit_group;");
    }

    // ---------- Phase 1: load + L2-normalize latent basis (k-duplicated layout) ----------
    {
        if (tid == 0) { s.ctr = 0; s.flag = 0; }
        const float* lbg = lb + (size_t)g * (4 * CCH);
        float v0 = lbg[tid], v1 = lbg[CCH + tid], v2 = lbg[2 * CCH + tid], v3 = lbg[3 * CCH + tid];
        float s0 = wsum(v0 * v0), s1 = wsum(v1 * v1), s2 = wsum(v2 * v2), s3 = wsum(v3 * v3);
        if (lane == 0) { s.red[wid] = s0; s.red[8 + wid] = s1; s.red[16 + wid] = s2; s.red[24 + wid] = s3; }
        __syncthreads();
        if (tid < 4) {
            float ss = 0.f;
#pragma unroll
            for (int j = 0; j < 8; ++j) ss += s.red[tid * 8 + j];
            s.scal[tid] = 1.0f / fmaxf(sqrtf(ss), 1e-12f);
        }
        __syncthreads();
        float ox = v0 * s.scal[0], oy = v1 * s.scal[1], oz = v2 * s.scal[2], ow = v3 * s.scal[3];
        *reinterpret_cast<float4*>(&s.lbn8[tid * 8 + 0]) = make_float4(ox, ox, oy, oy);
        *reinterpret_cast<float4*>(&s.lbn8[tid * 8 + 4]) = make_float4(oz, oz, ow, ow);
        __syncthreads();
    }

    // ---------- Phase 2: cp.async-pipelined stencil pass (smem ring) ----------
    {
        const int j = wid & 3, rp = wid >> 2;
        const bool act2 = (lane < 22);
        const int lr = act2 ? (lane / 11) : 0;
        const int q  = act2 ? (lane - 11 * lr) : 0;
        const int r  = rp * 2 + lr;
        const int ru = (r > 0) ? r - 1 : 0, rd = (r < 3) ? r + 1 : 3;
        const u64 fu2 = pk2((r > 0) ? 1.f : 0.f, (r > 0) ? 1.f : 0.f);
        const u64 fd2 = pk2((r < 3) ? 1.f : 0.f, (r < 3) ? 1.f : 0.f);
        const float fq0 = (q > 0) ? 1.f : 0.f, fq10 = (q < 10) ? 1.f : 0.f;
        const int po = r * WW + q * 4;

        u64 pd0a = 0, pd0b = 0, pd1a = 0, pd1b = 0, pd2a = 0, pd2b = 0, pd3a = 0, pd3b = 0;
        u64 fea = 0, feb = 0, nra = 0, nrb = 0;

#pragma unroll 1
        for (int it = 0; it < CCH / STCH; ++it) {
            asm volatile("cp.async.wait_group 2;");
            __syncthreads();
            if (it + 3 < CCH / STCH)
                fill_stage(ring + ((it + 3) & (NSTAGE - 1)) * SLOTF, xb, (it + 3) * STCH, tid);
            asm volatile("cp.async.commit_group;");

            const float* ch = ring + (it & (NSTAGE - 1)) * SLOTF + j * PPX;
            ulonglong2 xm = *reinterpret_cast<const ulonglong2*>(ch + r  * WW + q * 4);
            ulonglong2 xu = *reinterpret_cast<const ulonglong2*>(ch + ru * WW + q * 4);
            ulonglong2 xd = *reinterpret_cast<const ulonglong2*>(ch + rd * WW + q * 4);

            u64 vs01 = ffma2(xu.x, fu2, ffma2(xd.x, fd2, xm.x));
            u64 vs23 = ffma2(xu.y, fu2, ffma2(xd.y, fd2, xm.y));
            float v0, v1, v2, v3;
            up2(vs01, v0, v1); up2(vs23, v2, v3);
            float lw = __shfl_up_sync(FULL, v3, 1) * fq0;
            float rw = __shfl_down_sync(FULL, v0, 1) * fq10;
            u64 pl01 = pk2(lw + v0 + v1, v0 + v1 + v2);
            u64 pl23 = pk2(v1 + v2 + v3, v2 + v3 + rw);

            const ulonglong2* lb8 = reinterpret_cast<const ulonglong2*>(&s.lbn8[(it * STCH + j) * 8]);
            ulonglong2 lxy = lb8[0], lzw = lb8[1];
            pd0a = ffma2(pl01, lxy.x, pd0a); pd0b = ffma2(pl23, lxy.x, pd0b);
            pd1a = ffma2(pl01, lxy.y, pd1a); pd1b = ffma2(pl23, lxy.y, pd1b);
            pd2a = ffma2(pl01, lzw.x, pd2a); pd2b = ffma2(pl23, lzw.x, pd2b);
            pd3a = ffma2(pl01, lzw.y, pd3a); pd3b = ffma2(pl23, lzw.y, pd3b);
            fea = ffma2(xm.x, xm.x, fea);    feb = ffma2(xm.y, xm.y, feb);
            nra = ffma2(pl01, pl01, nra);    nrb = ffma2(pl23, pl23, nrb);
            __syncthreads();
        }
        if (act2) {
            float p0x, p0y, p0z, p0w, p1x, p1y, p1z, p1w;
            float p2x, p2y, p2z, p2w, p3x, p3y, p3z, p3w;
            up2(pd0a, p0x, p0y); up2(pd0b, p0z, p0w);
            up2(pd1a, p1x, p1y); up2(pd1b, p1z, p1w);
            up2(pd2a, p2x, p2y); up2(pd2b, p2z, p2w);
            up2(pd3a, p3x, p3y); up2(pd3b, p3z, p3w);
            float fx, fy, fz, fw, nx, ny, nz, nw;
            up2(fea, fx, fy); up2(feb, fz, fw);
            up2(nra, nx, ny); up2(nrb, nz, nw);
            float* pb = &s.pdP[(j * PPX + po) * 4];
            *reinterpret_cast<float4*>(pb + 0)  = make_float4(p0x, p1x, p2x, p3x);
            *reinterpret_cast<float4*>(pb + 4)  = make_float4(p0y, p1y, p2y, p3y);
            *reinterpret_cast<float4*>(pb + 8)  = make_float4(p0z, p1z, p2z, p3z);
            *reinterpret_cast<float4*>(pb + 12) = make_float4(p0w, p1w, p2w, p3w);
            *reinterpret_cast<float4*>(&s.feP[j * PPX + po])  = make_float4(fx, fy, fz, fw);
            *reinterpret_cast<float4*>(&s.nrmP[j * PPX + po]) = make_float4(nx, ny, nz, nw);
        }
    }
    __syncthreads();

    // ---------- Phase 2b: combine partials + fused fe-max ----------
    float dotv0 = 0, dotv1 = 0, dotv2 = 0, dotv3 = 0, fev = 0, nmv = 0;
    if (tid < PPX) {
#pragma unroll
        for (int cs = 0; cs < 4; ++cs) {
            float4 v = *reinterpret_cast<float4*>(&s.pdP[(cs * PPX + tid) * 4]);
            dotv0 += v.x; dotv1 += v.y; dotv2 += v.z; dotv3 += v.w;
            fev += s.feP[cs * PPX + tid];
            nmv += s.nrmP[cs * PPX + tid];
        }
        fev *= (1.0f / CCH);
        nmv *= (1.0f / 81.0f);
    }
    {
        float m = wmaxr((tid < PPX) ? fev : 0.f);
        if (lane == 0) s.red[wid] = m;
    }
    __syncthreads();
    float invmax;
    {
        float mm = s.red[0];
#pragma unroll
        for (int j = 1; j < 8; ++j) mm = fmaxf(mm, s.red[j]);
        invmax = 1.0f / fmaxf(mm, 1e-6f);
    }
    int pred = (tid < PPX) && (fev * invmax > GATE_THR);
    int cnt = __syncthreads_count(pred);

    // ---------- Phase 4: softmax routing -> support ----------
    if (tid < PPX) {
        float rn = 1.0f / fmaxf(sqrtf(nmv), 1e-12f);
        float sc = rn * TEMP_INV * (1.f / 9.f);
        float l0 = dotv0 * sc, l1 = dotv1 * sc, l2 = dotv2 * sc, l3 = dotv3 * sc;
        float m = fmaxf(fmaxf(l0, l1), fmaxf(l2, l3));
        float e0 = __expf(l0 - m), e1 = __expf(l1 - m), e2 = __expf(l2 - m), e3 = __expf(l3 - m);
        float inv = 1.0f / (e0 + e1 + e2 + e3);
        float fes = fev * invmax;
        float act = (cnt > 0) ? (fes > GATE_THR ? 1.f : 0.f) : (fes > 0.f ? 1.f : 0.f);
        float w_ = inv * act;
        *reinterpret_cast<float4*>(&s.sup[tid * 4]) = make_float4(e0 * w_, e1 * w_, e2 * w_, e3 * w_);
    }
    __syncthreads();

    // ---------- Phase 5: overlapped tail ----------
    float* smb = out_smap + (size_t)n * (HW * 64) + (size_t)g * (PPX * 64);
    float* pmb = out_pmap + (size_t)n * (HW * 64) + (size_t)g * (PPX * 64);

    if (wid == 0) {
        float s0 = 0, s1 = 0, s2 = 0, s3 = 0;
        for (int pp = lane; pp < PPX; pp += 32) {
            float4 v = *reinterpret_cast<float4*>(&s.sup[pp * 4]);
            s0 += v.x; s1 += v.y; s2 += v.z; s3 += v.w;
        }
        s0 = wsum(s0); s1 = wsum(s1); s2 = wsum(s2); s3 = wsum(s3);
        float i0 = 1.0f / fmaxf(s0, 1e-6f), i1 = 1.0f / fmaxf(s1, 1e-6f);
        float i2 = 1.0f / fmaxf(s2, 1e-6f), i3 = 1.0f / fmaxf(s3, 1e-6f);
        for (int pp = lane; pp < PPX; pp += 32) {
            float4 v = *reinterpret_cast<float4*>(&s.sup[pp * 4]);
            float4 w = make_float4(v.x * i0, v.y * i1, v.z * i2, v.w * i3);
            *reinterpret_cast<float4*>(&s.pw[pp * 4]) = w;
            s.pwT[0 * PPX + pp] = w.x;
            s.pwT[1 * PPX + pp] = w.y;
            s.pwT[2 * PPX + pp] = w.z;
            s.pwT[3 * PPX + pp] = w.w;
        }
        __threadfence_block();
        if (lane == 0) s.flag = 1;
    } else if (wid >= 4) {
        const int k = wid - 4;
        float v[6];
#pragma unroll
        for (int j = 0; j < 6; ++j) {
            int pp = lane + 32 * j;
            v[j] = (pp < PPX) ? s.sup[pp * 4 + k] : -1.0f;
        }
        float sum = 0.f;
        for (int it = 0; it < TOPKK; ++it) {
            float lm = v[0]; int li = 0;
#pragma unroll
            for (int j = 1; j < 6; ++j) { if (v[j] > lm) { lm = v[j]; li = j; } }
            float wm = wmaxr(lm);
            unsigned msk = __ballot_sync(FULL, lm == wm);
            int src = __ffs(msk) - 1;
            if (lane == src) v[li] = -1.0f;
            sum += wm;
        }
        if (lane == 0) {
            out_pres[n * 64 + g * 4 + k] = sum * (1.0f / TOPKK);
            __threadfence();
        }
    }

    // work queue: units [0,22)=smap, [22,86)=tokens, [86,108)=pmap
    {
        const float4 z4 = make_float4(0.f, 0.f, 0.f, 0.f);
        bool pwReady = false;
        for (;;) {
            int u;
            if (lane == 0) u = atomicAdd(&s.ctr, 1);
            u = __shfl_sync(FULL, u, 0);
            if (u >= NUNITS) break;
            if (u >= 22 && !pwReady) {
                while (*((volatile int*)&s.flag) == 0) {}
                __threadfence_block();
                pwReady = true;
            }
            if (u < 22) {
                int base = u * 128;
#pragma unroll
                for (int j = 0; j < 4; ++j) {
                    int idx = base + j * 32 + lane;
                    int pp = idx >> 4, qd = idx & 15;
                    float4 sv = (qd == g) ? *reinterpret_cast<float4*>(&s.sup[pp * 4]) : z4;
                    *reinterpret_cast<float4*>(smb + (size_t)idx * 4) = sv;
                }
            } else if (u < 86) {
                const int grp = lane >> 3, gl = lane & 7;
                const int c = (u - 22) * 4 + grp;
                const float* xc = xb + (size_t)c * HW;
                u64 a0 = 0, a1 = 0, a2 = 0, a3 = 0;
#pragma unroll
                for (int it = 0; it < 6; ++it) {
                    int p0 = it * 32 + gl * 4;
                    if (p0 < PPX) {
                        ulonglong2 xv = *reinterpret_cast<const ulonglong2*>(xc + p0);
                        ulonglong2 w0 = *reinterpret_cast<const ulonglong2*>(&s.pwT[0 * PPX + p0]);
                        ulonglong2 w1 = *reinterpret_cast<const ulonglong2*>(&s.pwT[1 * PPX + p0]);
                        ulonglong2 w2 = *reinterpret_cast<const ulonglong2*>(&s.pwT[2 * PPX + p0]);
                        ulonglong2 w3 = *reinterpret_cast<const ulonglong2*>(&s.pwT[3 * PPX + p0]);
                        a0 = ffma2(xv.y, w0.y, ffma2(xv.x, w0.x, a0));
                        a1 = ffma2(xv.y, w1.y, ffma2(xv.x, w1.x, a1));
                        a2 = ffma2(xv.y, w2.y, ffma2(xv.x, w2.x, a2));
                        a3 = ffma2(xv.y, w3.y, ffma2(xv.x, w3.x, a3));
                    }
                }
                float x0, y0, x1, y1, x2, y2, x3, y3;
                up2(a0, x0, y0); up2(a1, x1, y1); up2(a2, x2, y2); up2(a3, x3, y3);
                float f0 = x0 + y0, f1 = x1 + y1, f2 = x2 + y2, f3 = x3 + y3;
#pragma unroll
                for (int m = 1; m <= 4; m <<= 1) {
                    f0 += __shfl_xor_sync(FULL, f0, m);
                    f1 += __shfl_xor_sync(FULL, f1, m);
                    f2 += __shfl_xor_sync(FULL, f2, m);
                    f3 += __shfl_xor_sync(FULL, f3, m);
                }
                if (gl == 0)
                    *reinterpret_cast<float4*>(out_tok + ((size_t)(n * CCH + c) * 64 + g * 4)) =
                        make_float4(f0, f1, f2, f3);
            } else {
                int base = (u - 86) * 128;
#pragma unroll
                for (int j = 0; j < 4; ++j) {
                    int idx = base + j * 32 + lane;
                    int pp = idx >> 4, qd = idx & 15;
                    float4 pv = (qd == g) ? *reinterpret_cast<float4*>(&s.pw[pp * 4]) : z4;
                    *reinterpret_cast<float4*>(pmb + (size_t)idx * 4) = pv;
                }
            }
        }
    }

    // ---------- Phase 9: last CTA of batch n normalizes presence ----------
    __syncthreads();
    if (tid == 0) {
        __threadfence();
        int old = atomicAdd(&g_cnt[n], 1);
        s.red[0] = (old == 15) ? 1.f : 0.f;
    }
    __syncthreads();
    if (s.red[0] != 0.f && wid == 0) {
        __threadfence();
        float a = out_pres[n * 64 + lane];
        float b = out_pres[n * 64 + 32 + lane];
        float t = wsum(a + b);
        float inv = 1.0f / fmaxf(t, 1e-6f);
        out_pres[n * 64 + lane] = a * inv;
        out_pres[n * 64 + 32 + lane] = b * inv;
        if (lane == 0) g_cnt[n] = 0;
    }
}

extern "C" void kernel_launch(void* const* d_in, const int* in_sizes, int n_in,
                              void* d_out, int out_size)
{
    const float* x  = (const float*)d_in[0];
    const float* lb = (const float*)d_in[1];
    float* out = (float*)d_out;

    float* tok  = out;
    float* pres = out + TOK_ELEMS;
    float* smap = out + TOK_ELEMS + PRES_ELEMS;
    float* pmap = out + TOK_ELEMS + PRES_ELEMS + MAP_ELEMS;

    cudaFuncSetAttribute(fused_stripe_kernel,
                         cudaFuncAttributeMaxDynamicSharedMemorySize, SMEM_TOTAL);
    fused_stripe_kernel<<<NB * 16, THREADS, SMEM_TOTAL>>>(x, lb, tok, pres, smap, pmap);
}